// round 10
// baseline (speedup 1.0000x reference)
#include <cuda_runtime.h>

// FraudDetectionHybrid — autoencoder branch is dead code (recon unused).
// R10: MUFU reciprocal-throughput is the binder (R7/R8/R9 all flat at equal
// MUFU-cycle load). Remove 6 of 14 MUFU/sample: conv+sampler+softmax is a
// smooth G(h0,h1) on (-1,1)^2 -> precompute 513x513 table (kernel 1, ~0.7us),
// bilinear-lookup in the main kernel. Fraud stack back to full f32 tanh.

#define TAB_N 513                 // grid points per axis, spacing 1/256
__device__ float g_tab[TAB_N * TAB_N];   // 1.05 MB, L2-resident

__device__ __forceinline__ float tanh_fast(float x) {
    float y;
    asm("tanh.approx.f32 %0, %1;" : "=f"(y) : "f"(x));
    return y;
}

// ---------------- kernel 1: build G(h0,h1) table ----------------
__global__ __launch_bounds__(256)
void build_table(const float4* __restrict__ conv_k,    // [2,2] = 1 float4
                 const float4* __restrict__ s_W1,      // [4,2] = 2 float4
                 const float4* __restrict__ s_b1,      // [4]   = 1 float4
                 const float4* __restrict__ s_W2,      // [2,4] = 2 float4
                 const float2* __restrict__ s_b2)      // [2]   = 1 float2
{
    const int idx = blockIdx.x * blockDim.x + threadIdx.x;
    if (idx >= TAB_N * TAB_N) return;
    const int ix = idx % TAB_N;          // h0 axis
    const int iy = idx / TAB_N;          // h1 axis
    const float h0 = (float)ix * (1.0f / 256.0f) - 1.0f;
    const float h1 = (float)iy * (1.0f / 256.0f) - 1.0f;

    const float4 ck  = __ldg(conv_k);
    const float4 W1a = __ldg(s_W1 + 0);
    const float4 W1b = __ldg(s_W1 + 1);
    const float4 b1  = __ldg(s_b1);
    const float4 W2a = __ldg(s_W2 + 0);
    const float4 W2b = __ldg(s_W2 + 1);
    const float2 b2  = __ldg(s_b2);

    const float c0  = ck.x + ck.z;
    const float c1  = ck.y + ck.w;
    const float dW0 = W2b.x - W2a.x;
    const float dW1 = W2b.y - W2a.y;
    const float dW2 = W2b.z - W2a.z;
    const float dW3 = W2b.w - W2a.w;
    const float db  = b2.y - b2.x;

    float zc   = fmaf(c0, h0, c1 * h1);
    float conv = fmaf(tanh_fast(0.5f * zc), 0.5f, 0.5f);
    float t0 = tanh_fast(fmaf(W1a.x, h0, fmaf(W1a.y, conv, b1.x)));
    float t1 = tanh_fast(fmaf(W1a.z, h0, fmaf(W1a.w, conv, b1.y)));
    float t2 = tanh_fast(fmaf(W1b.x, h0, fmaf(W1b.y, conv, b1.z)));
    float t3 = tanh_fast(fmaf(W1b.z, h0, fmaf(W1b.w, conv, b1.w)));
    float dl = fmaf(t3, dW3, fmaf(t2, dW2, fmaf(t1, dW1, fmaf(t0, dW0, db))));
    // p0 = sigmoid(-dl) = 0.5 - 0.5*tanh(dl/2)
    g_tab[idx] = fmaf(tanh_fast(0.5f * dl), -0.5f, 0.5f);
}

// ---------------- kernel 2: fraud stack + bilinear lookup ----------------
__global__ __launch_bounds__(256, 6)
void fraud_kernel(const float4* __restrict__ x4,
                  const float4* __restrict__ fraud_W,   // [4,2,2] = 4 float4
                  const float4* __restrict__ fraud_b,   // [4,2]   = 2 float4
                  float4* __restrict__ out4,
                  int n4)
{
    const int t = blockIdx.x * blockDim.x + threadIdx.x;
    if (t >= n4) return;

    const float4 in = x4[t];

    const float4 w0  = __ldg(fraud_W + 0);
    const float4 w1  = __ldg(fraud_W + 1);
    const float4 w2  = __ldg(fraud_W + 2);
    const float4 w3  = __ldg(fraud_W + 3);
    const float4 fb0 = __ldg(fraud_b + 0);
    const float4 fb1 = __ldg(fraud_b + 1);

    auto process = [&](float h0, float h1, float& p0, float& p1) {
        // fraud net: 4 stacked 2x2 affine + f32 MUFU tanh
        float z0 = fmaf(w0.x, h0, fmaf(w0.y, h1, fb0.x));
        float z1 = fmaf(w0.z, h0, fmaf(w0.w, h1, fb0.y));
        h0 = tanh_fast(z0); h1 = tanh_fast(z1);
        z0 = fmaf(w1.x, h0, fmaf(w1.y, h1, fb0.z));
        z1 = fmaf(w1.z, h0, fmaf(w1.w, h1, fb0.w));
        h0 = tanh_fast(z0); h1 = tanh_fast(z1);
        z0 = fmaf(w2.x, h0, fmaf(w2.y, h1, fb1.x));
        z1 = fmaf(w2.z, h0, fmaf(w2.w, h1, fb1.y));
        h0 = tanh_fast(z0); h1 = tanh_fast(z1);
        z0 = fmaf(w3.x, h0, fmaf(w3.y, h1, fb1.z));
        z1 = fmaf(w3.z, h0, fmaf(w3.w, h1, fb1.w));
        h0 = tanh_fast(z0); h1 = tanh_fast(z1);

        // bilinear lookup of G(h0,h1): u,v in [0,512]
        float u = fmaf(h0, 256.0f, 256.0f);
        float v = fmaf(h1, 256.0f, 256.0f);
        int ix = __float2int_rd(u);
        int iy = __float2int_rd(v);
        ix = max(0, min(ix, TAB_N - 2));
        iy = max(0, min(iy, TAB_N - 2));
        float fx = u - (float)ix;
        float fy = v - (float)iy;
        const float* row0 = g_tab + iy * TAB_N + ix;
        float v00 = __ldg(row0);
        float v01 = __ldg(row0 + 1);
        float v10 = __ldg(row0 + TAB_N);
        float v11 = __ldg(row0 + TAB_N + 1);
        float g0 = fmaf(fx, v01 - v00, v00);
        float g1 = fmaf(fx, v11 - v10, v10);
        p0 = fmaf(fy, g1 - g0, g0);
        p1 = 1.0f - p0;
    };

    float pa0, pa1, pb0, pb1;
    process(in.x, in.y, pa0, pa1);
    process(in.z, in.w, pb0, pb1);
    out4[t] = make_float4(pa0, pa1, pb0, pb1);
}

extern "C" void kernel_launch(void* const* d_in, const int* in_sizes, int n_in,
                              void* d_out, int out_size)
{
    // kernel 1: build the G table (263k cells)
    const int tab_cells = TAB_N * TAB_N;
    build_table<<<(tab_cells + 255) / 256, 256>>>(
        (const float4*)d_in[15],           // conv_k
        (const float4*)d_in[16],           // s_W1
        (const float4*)d_in[17],           // s_b1
        (const float4*)d_in[18],           // s_W2
        (const float2*)d_in[19]);          // s_b2

    // kernel 2: main
    const int n4 = in_sizes[0] / 4;        // float4 count (2 samples each)
    const int block = 256;
    const int grid = (n4 + block - 1) / block;
    fraud_kernel<<<grid, block>>>(
        (const float4*)d_in[0],            // x
        (const float4*)d_in[1],            // fraud_W
        (const float4*)d_in[2],            // fraud_b
        (float4*)d_out,
        n4);
}

// round 11
// speedup vs baseline: 1.1604x; 1.1604x over previous
#include <cuda_runtime.h>

// FraudDetectionHybrid — autoencoder branch is dead code (recon unused).
// R11: R10's table idea was right (interp err tiny) but global-memory gather
// caused an L1tex wavefront storm (issue 21%). Move the G(h0,h1) table to
// SHARED memory: N=81 grid (26KB/block), bilinear via 4 LDS (smem gather has
// no wavefront replay pathology). MUFU: 14 -> 8 tanh/sample (fraud stack only,
// full f32). block=512, grid=512 -> 4 blocks/SM, occ 100%, single wave.

#define TAB_N   81
#define TAB_PAD 6564                    // 81*81=6561 padded to /4
__device__ float g_tab[TAB_PAD];

__device__ __forceinline__ float tanh_fast(float x) {
    float y;
    asm("tanh.approx.f32 %0, %1;" : "=f"(y) : "f"(x));
    return y;
}

// ---------------- kernel 1: build G(h0,h1) table (tiny) ----------------
__global__ __launch_bounds__(256)
void build_table(const float4* __restrict__ conv_k,    // [2,2] = 1 float4
                 const float4* __restrict__ s_W1,      // [4,2] = 2 float4
                 const float4* __restrict__ s_b1,      // [4]   = 1 float4
                 const float4* __restrict__ s_W2,      // [2,4] = 2 float4
                 const float2* __restrict__ s_b2)      // [2]   = 1 float2
{
    const int idx = blockIdx.x * blockDim.x + threadIdx.x;
    if (idx >= TAB_N * TAB_N) return;
    const int ix = idx % TAB_N;          // h0 axis
    const int iy = idx / TAB_N;          // h1 axis
    const float h0 = (float)ix * (1.0f / 40.0f) - 1.0f;
    const float h1 = (float)iy * (1.0f / 40.0f) - 1.0f;

    const float4 ck  = __ldg(conv_k);
    const float4 W1a = __ldg(s_W1 + 0);
    const float4 W1b = __ldg(s_W1 + 1);
    const float4 b1  = __ldg(s_b1);
    const float4 W2a = __ldg(s_W2 + 0);
    const float4 W2b = __ldg(s_W2 + 1);
    const float2 b2  = __ldg(s_b2);

    const float c0  = ck.x + ck.z;
    const float c1  = ck.y + ck.w;
    const float dW0 = W2b.x - W2a.x;
    const float dW1 = W2b.y - W2a.y;
    const float dW2 = W2b.z - W2a.z;
    const float dW3 = W2b.w - W2a.w;
    const float db  = b2.y - b2.x;

    float zc   = fmaf(c0, h0, c1 * h1);
    float conv = fmaf(tanh_fast(0.5f * zc), 0.5f, 0.5f);
    float t0 = tanh_fast(fmaf(W1a.x, h0, fmaf(W1a.y, conv, b1.x)));
    float t1 = tanh_fast(fmaf(W1a.z, h0, fmaf(W1a.w, conv, b1.y)));
    float t2 = tanh_fast(fmaf(W1b.x, h0, fmaf(W1b.y, conv, b1.z)));
    float t3 = tanh_fast(fmaf(W1b.z, h0, fmaf(W1b.w, conv, b1.w)));
    float dl = fmaf(t3, dW3, fmaf(t2, dW2, fmaf(t1, dW1, fmaf(t0, dW0, db))));
    // p0 = sigmoid(-dl) = 0.5 - 0.5*tanh(dl/2)
    g_tab[idx] = fmaf(tanh_fast(0.5f * dl), -0.5f, 0.5f);
}

// ---------------- kernel 2: fraud stack + smem bilinear ----------------
__global__ __launch_bounds__(512, 4)
void fraud_kernel(const float4* __restrict__ x4,
                  const float4* __restrict__ fraud_W,   // [4,2,2] = 4 float4
                  const float4* __restrict__ fraud_b,   // [4,2]   = 2 float4
                  float4* __restrict__ out4,
                  int n4)
{
    __shared__ float tab[TAB_PAD];

    // cooperative table load: 1641 float4 over 512 threads
    {
        const float4* src = reinterpret_cast<const float4*>(g_tab);
        float4* dst = reinterpret_cast<float4*>(tab);
#pragma unroll
        for (int i = threadIdx.x; i < TAB_PAD / 4; i += 512)
            dst[i] = src[i];
    }

    const int t = blockIdx.x * blockDim.x + threadIdx.x;
    const float4 in = (t < n4) ? x4[t] : make_float4(0.f, 0.f, 0.f, 0.f);

    const float4 w0  = __ldg(fraud_W + 0);
    const float4 w1  = __ldg(fraud_W + 1);
    const float4 w2  = __ldg(fraud_W + 2);
    const float4 w3  = __ldg(fraud_W + 3);
    const float4 fb0 = __ldg(fraud_b + 0);
    const float4 fb1 = __ldg(fraud_b + 1);

    __syncthreads();
    if (t >= n4) return;

    auto process = [&](float h0, float h1, float& p0, float& p1) {
        // fraud net: 4 stacked 2x2 affine + f32 MUFU tanh
        float z0 = fmaf(w0.x, h0, fmaf(w0.y, h1, fb0.x));
        float z1 = fmaf(w0.z, h0, fmaf(w0.w, h1, fb0.y));
        h0 = tanh_fast(z0); h1 = tanh_fast(z1);
        z0 = fmaf(w1.x, h0, fmaf(w1.y, h1, fb0.z));
        z1 = fmaf(w1.z, h0, fmaf(w1.w, h1, fb0.w));
        h0 = tanh_fast(z0); h1 = tanh_fast(z1);
        z0 = fmaf(w2.x, h0, fmaf(w2.y, h1, fb1.x));
        z1 = fmaf(w2.z, h0, fmaf(w2.w, h1, fb1.y));
        h0 = tanh_fast(z0); h1 = tanh_fast(z1);
        z0 = fmaf(w3.x, h0, fmaf(w3.y, h1, fb1.z));
        z1 = fmaf(w3.z, h0, fmaf(w3.w, h1, fb1.w));
        h0 = tanh_fast(z0); h1 = tanh_fast(z1);

        // bilinear lookup of G(h0,h1) in smem; u,v in [0,80]
        float u = fmaf(h0, 40.0f, 40.0f);
        float v = fmaf(h1, 40.0f, 40.0f);
        int ix = min(__float2int_rd(u), TAB_N - 2);
        int iy = min(__float2int_rd(v), TAB_N - 2);
        float fx = u - (float)ix;
        float fy = v - (float)iy;
        const float* row0 = tab + iy * TAB_N + ix;
        float v00 = row0[0];
        float v01 = row0[1];
        float v10 = row0[TAB_N];
        float v11 = row0[TAB_N + 1];
        float g0 = fmaf(fx, v01 - v00, v00);
        float g1 = fmaf(fx, v11 - v10, v10);
        p0 = fmaf(fy, g1 - g0, g0);
        p1 = 1.0f - p0;
    };

    float pa0, pa1, pb0, pb1;
    process(in.x, in.y, pa0, pa1);
    process(in.z, in.w, pb0, pb1);
    out4[t] = make_float4(pa0, pa1, pb0, pb1);
}

extern "C" void kernel_launch(void* const* d_in, const int* in_sizes, int n_in,
                              void* d_out, int out_size)
{
    // kernel 1: build the 81x81 G table (6561 cells)
    build_table<<<(TAB_N * TAB_N + 255) / 256, 256>>>(
        (const float4*)d_in[15],           // conv_k
        (const float4*)d_in[16],           // s_W1
        (const float4*)d_in[17],           // s_b1
        (const float4*)d_in[18],           // s_W2
        (const float2*)d_in[19]);          // s_b2

    // kernel 2: main
    const int n4 = in_sizes[0] / 4;        // float4 count (2 samples each) = 262144
    const int block = 512;
    const int grid = (n4 + block - 1) / block;   // 512 blocks
    fraud_kernel<<<grid, block>>>(
        (const float4*)d_in[0],            // x
        (const float4*)d_in[1],            // fraud_W
        (const float4*)d_in[2],            // fraud_b
        (float4*)d_out,
        n4);
}

// round 12
// speedup vs baseline: 1.3499x; 1.1633x over previous
#include <cuda_runtime.h>

// FraudDetectionHybrid — autoencoder branch is dead code (recon unused).
// R12: falsified so far: MUFU count (R9,R11), occupancy alone (R8), tables
// (R10,R11), multi-node graphs (R4,R10,R11). What correlates with speed:
// weight-load amortization + single-wave launch (R4 7.90us was the best).
// This round: single kernel node, 8 samples/thread (weights amortized 8x),
// block=256 grid=512 -> 3.46 blocks/SM, single wave, MLP=4 input loads
// up-front, streaming load/store hints, proven f32 MUFU math throughout.

__device__ __forceinline__ float tanh_fast(float x) {
    float y;
    asm("tanh.approx.f32 %0, %1;" : "=f"(y) : "f"(x));
    return y;
}

__global__ __launch_bounds__(256, 4)
void fraud_kernel(const float4* __restrict__ x4,
                  const float4* __restrict__ fraud_W,   // [4,2,2] = 4 float4
                  const float4* __restrict__ fraud_b,   // [4,2]   = 2 float4
                  const float4* __restrict__ conv_k,    // [2,2]   = 1 float4
                  const float4* __restrict__ s_W1,      // [4,2]   = 2 float4
                  const float4* __restrict__ s_b1,      // [4]     = 1 float4
                  const float4* __restrict__ s_W2,      // [2,4]   = 2 float4
                  const float2* __restrict__ s_b2,      // [2]     = 1 float2
                  float4* __restrict__ out4)
{
    // grid 512 x block 256; each thread owns 4 float4 (8 samples),
    // strided by 256 within a 1024-float4 block tile -> fully coalesced.
    const int base = blockIdx.x * 1024 + threadIdx.x;

    // ---- 4 input loads in flight first (read-once: streaming) ----
    const float4 in0 = __ldcs(x4 + base);
    const float4 in1 = __ldcs(x4 + base + 256);
    const float4 in2 = __ldcs(x4 + base + 512);
    const float4 in3 = __ldcs(x4 + base + 768);

    // ---- broadcast weight loads (uniform addresses, L1-hit) ----
    const float4 w0  = __ldg(fraud_W + 0);
    const float4 w1  = __ldg(fraud_W + 1);
    const float4 w2  = __ldg(fraud_W + 2);
    const float4 w3  = __ldg(fraud_W + 3);
    const float4 fb0 = __ldg(fraud_b + 0);
    const float4 fb1 = __ldg(fraud_b + 1);
    const float4 ck  = __ldg(conv_k);
    const float4 W1a = __ldg(s_W1 + 0);
    const float4 W1b = __ldg(s_W1 + 1);
    const float4 b1  = __ldg(s_b1);
    const float4 W2a = __ldg(s_W2 + 0);
    const float4 W2b = __ldg(s_W2 + 1);
    const float2 b2  = __ldg(s_b2);

    const float c0  = ck.x + ck.z;
    const float c1  = ck.y + ck.w;
    const float dW0 = W2b.x - W2a.x;
    const float dW1 = W2b.y - W2a.y;
    const float dW2 = W2b.z - W2a.z;
    const float dW3 = W2b.w - W2a.w;
    const float db  = b2.y - b2.x;

    auto process = [&](float h0, float h1, float& p0, float& p1) {
        // fraud net: 4 stacked 2x2 affine + f32 MUFU tanh
        float z0 = fmaf(w0.x, h0, fmaf(w0.y, h1, fb0.x));
        float z1 = fmaf(w0.z, h0, fmaf(w0.w, h1, fb0.y));
        h0 = tanh_fast(z0); h1 = tanh_fast(z1);
        z0 = fmaf(w1.x, h0, fmaf(w1.y, h1, fb0.z));
        z1 = fmaf(w1.z, h0, fmaf(w1.w, h1, fb0.w));
        h0 = tanh_fast(z0); h1 = tanh_fast(z1);
        z0 = fmaf(w2.x, h0, fmaf(w2.y, h1, fb1.x));
        z1 = fmaf(w2.z, h0, fmaf(w2.w, h1, fb1.y));
        h0 = tanh_fast(z0); h1 = tanh_fast(z1);
        z0 = fmaf(w3.x, h0, fmaf(w3.y, h1, fb1.z));
        z1 = fmaf(w3.z, h0, fmaf(w3.w, h1, fb1.w));
        h0 = tanh_fast(z0); h1 = tanh_fast(z1);
        // collapsed 2x2 conv + sigmoid via tanh
        float zc   = fmaf(c0, h0, c1 * h1);
        float conv = fmaf(tanh_fast(0.5f * zc), 0.5f, 0.5f);
        // sampler: 2 -> 4 (tanh)
        float t0 = tanh_fast(fmaf(W1a.x, h0, fmaf(W1a.y, conv, b1.x)));
        float t1 = tanh_fast(fmaf(W1a.z, h0, fmaf(W1a.w, conv, b1.y)));
        float t2 = tanh_fast(fmaf(W1b.x, h0, fmaf(W1b.y, conv, b1.z)));
        float t3 = tanh_fast(fmaf(W1b.z, h0, fmaf(W1b.w, conv, b1.w)));
        // 2-way softmax == sigmoid of logit difference
        float dl = fmaf(t3, dW3, fmaf(t2, dW2, fmaf(t1, dW1, fmaf(t0, dW0, db))));
        float s  = tanh_fast(0.5f * dl);
        p1 = fmaf(s,  0.5f, 0.5f);
        p0 = fmaf(s, -0.5f, 0.5f);
    };

    float4 r0, r1, r2, r3;
    process(in0.x, in0.y, r0.x, r0.y);
    process(in0.z, in0.w, r0.z, r0.w);
    process(in1.x, in1.y, r1.x, r1.y);
    process(in1.z, in1.w, r1.z, r1.w);
    process(in2.x, in2.y, r2.x, r2.y);
    process(in2.z, in2.w, r2.z, r2.w);
    process(in3.x, in3.y, r3.x, r3.y);
    process(in3.z, in3.w, r3.z, r3.w);

    __stcs(out4 + base,       r0);
    __stcs(out4 + base + 256, r1);
    __stcs(out4 + base + 512, r2);
    __stcs(out4 + base + 768, r3);
}

extern "C" void kernel_launch(void* const* d_in, const int* in_sizes, int n_in,
                              void* d_out, int out_size)
{
    const int block = 256;
    const int grid = 512;               // 524288 float4 / (256 thr * 4 f4/thr)
    fraud_kernel<<<grid, block>>>(
        (const float4*)d_in[0],         // x
        (const float4*)d_in[1],         // fraud_W
        (const float4*)d_in[2],         // fraud_b
        (const float4*)d_in[15],        // conv_k
        (const float4*)d_in[16],        // s_W1
        (const float4*)d_in[17],        // s_b1
        (const float4*)d_in[18],        // s_W2
        (const float2*)d_in[19],        // s_b2
        (float4*)d_out);
}